// round 16
// baseline (speedup 1.0000x reference)
#include <cuda_runtime.h>
#include <cuda_fp16.h>
#include <math.h>
#include <stdint.h>

#define SEQ  4096
#define DIN  1024
#define DOUT 1024

// ---------------- scratch (__device__ globals, alloc-free rule) ----------------
__device__ __half g_inH[(size_t)SEQ * DIN];            // half(input)
__device__ __half g_WallH[(size_t)DIN * (3 * DOUT)];   // [W~q | W~k | W~v] centered, NN layout
__device__ __half g_QKVH[(size_t)SEQ * (3 * DOUT)];    // [q~ | k~ | v~] half
__device__ float  g_S[(size_t)SEQ * SEQ];              // fp32 scores
__device__ __half g_PH[(size_t)SEQ * SEQ];             // half unnorm probs
__device__ float  g_invS[SEQ];                         // 1/rowsum
__device__ float  g_tRow[SEQ];                         // sum_j exp_j * s_j
__device__ unsigned g_rowMax[SEQ];                     // monotone-keyed row max
__device__ float  g_a[DOUT], g_b[DOUT], g_cv[DOUT];    // col means of Wq, Wk, Wv
__device__ float  g_ab[1];                             // a . b
__device__ float  g_gqr[DIN], g_gkr[DIN];              // Wq b (raw), Wk a (raw)
__device__ float  g_sRow[SEQ];                         // s_i = rowsum(input)
__device__ float  g_colAdd[SEQ];                       // = in_i . gk_raw
__device__ float  g_zRow[SEQ];                         // = in_i . gq_raw - ab*s_i

#define KEY_NEG_INF 0x007FFFFFu

// ---------------- helpers ----------------
__device__ __forceinline__ unsigned fkey(float f) {
    unsigned b = __float_as_uint(f);
    return (b & 0x80000000u) ? ~b : (b | 0x80000000u);
}
__device__ __forceinline__ float funkey(unsigned k) {
    unsigned b = (k & 0x80000000u) ? (k & 0x7FFFFFFFu) : ~k;
    return __uint_as_float(b);
}
#define CP_ASYNC16(saddr, gaddr) \
    asm volatile("cp.async.cg.shared.global [%0], [%1], 16;" :: "r"(saddr), "l"(gaddr))
#define CP_COMMIT() asm volatile("cp.async.commit_group;" ::: "memory")
#define CP_WAIT_GROUP(n) asm volatile("cp.async.wait_group " #n ";" ::: "memory")

__device__ __forceinline__ uint32_t smem_u32(const void* p) {
    uint32_t a;
    asm("{ .reg .u64 t; cvta.to.shared.u64 t, %1; cvt.u32.u64 %0, t; }" : "=r"(a) : "l"(p));
    return a;
}
#define LDSM_X4(r0, r1, r2, r3, addr) \
    asm volatile("ldmatrix.sync.aligned.m8n8.x4.shared.b16 {%0,%1,%2,%3}, [%4];" \
                 : "=r"(r0), "=r"(r1), "=r"(r2), "=r"(r3) : "r"(addr))
#define LDSM_X4_T(r0, r1, r2, r3, addr) \
    asm volatile("ldmatrix.sync.aligned.m8n8.x4.trans.shared.b16 {%0,%1,%2,%3}, [%4];" \
                 : "=r"(r0), "=r"(r1), "=r"(r2), "=r"(r3) : "r"(addr))

__device__ __forceinline__ void mma_f16(float* d,
                                        uint32_t a0, uint32_t a1, uint32_t a2, uint32_t a3,
                                        uint32_t b0, uint32_t b1) {
    asm volatile("mma.sync.aligned.m16n8k16.row.col.f32.f16.f16.f32 "
                 "{%0,%1,%2,%3}, {%4,%5,%6,%7}, {%8,%9}, {%0,%1,%2,%3};"
                 : "+f"(d[0]), "+f"(d[1]), "+f"(d[2]), "+f"(d[3])
                 : "r"(a0), "r"(a1), "r"(a2), "r"(a3), "r"(b0), "r"(b1));
}

// ---------------- tile geometry ----------------
#define PADH 40
#define OPH_HALFS (128 * PADH)
#define OPH_BYTES (OPH_HALFS * 2)         // 10240
#define STAGEH_BYTES (2 * OPH_BYTES)      // 20480 (NT 128x128)
#define NSTAGE_H 4
// NN B tile: 32 k-rows x 128 n, padded stride 136 halfs
#define PADB 136
#define OPB_BYTES (32 * PADB * 2)         // 8704
#define STAGE_NN (OPH_BYTES + OPB_BYTES)  // 18944
// scores N=64 tile: B = 64 rows x 40 halfs
#define OPB64_BYTES (64 * PADH * 2)       // 5120
#define STAGE_S64 (OPH_BYTES + OPB64_BYTES) // 15360

// ---- NN mainloop prolog (A NT rows, B [k][n] + ldmatrix.trans), 128x128 ----
#define GEMM_NN_PROLOG()                                                           \
    extern __shared__ __half smh[];                                                \
    const uint32_t sbase = smem_u32(smh);                                          \
    const int gx = gridDim.x, gy = gridDim.y;                                      \
    const int lin = blockIdx.y * gx + blockIdx.x;                                  \
    const int GROUP = 8;                                                           \
    const int per = GROUP * gx;                                                    \
    const int g = lin / per;                                                       \
    const int rem = lin - g * per;                                                 \
    const int rowsLeft = gy - g * GROUP;                                           \
    const int rows = (GROUP < rowsLeft) ? GROUP : rowsLeft;                        \
    const int byi = g * GROUP + rem % rows;                                        \
    const int bxi = rem / rows;                                                    \
    const int tid  = threadIdx.x;                                                  \
    const int lane = tid & 31;                                                     \
    const int wid  = tid >> 5;                                                     \
    const int warpM = wid >> 2;                                                    \
    const int warpN = wid & 3;                                                     \
    const int gID  = lane >> 2;                                                    \
    const int tig  = lane & 3;                                                     \
    const int rowBase = byi * 128;                                                 \
    const int colBase = bxi * 128;                                                 \
    const int lt = lane >> 3;                                                      \
    const int l7 = lane & 7;                                                       \
    const int aOff  = ((lt & 1) * 8 + l7) * PADH + (lt >> 1) * 8;                  \
    const int bOffT = ((lt & 1) * 8 + l7) * PADB + (lt >> 1) * 8;                  \
    const int ldRow0 = tid >> 2;                                                   \
    const int ldSeg  = tid & 3;                                                    \
    const int bRow   = tid >> 4;                                                   \
    const int bSeg   = tid & 15;                                                   \
    auto load_stage = [&](int st, int k0) {                                        \
        const uint32_t sA = sbase + st * STAGE_NN;                                 \
        const uint32_t sB = sA + OPH_BYTES;                                        \
        _Pragma("unroll")                                                          \
        for (int i = 0; i < 2; i++) {                                              \
            const int row = ldRow0 + i * 64;                                       \
            CP_ASYNC16(sA + (row * PADH + ldSeg * 8) * 2,                          \
                       A + (size_t)(rowBase + row) * lda + k0 + ldSeg * 8);        \
        }                                                                          \
        _Pragma("unroll")                                                          \
        for (int i = 0; i < 2; i++) {                                              \
            const int row = bRow + i * 16;                                         \
            CP_ASYNC16(sB + (row * PADB + bSeg * 8) * 2,                           \
                       B + (size_t)(k0 + row) * ldb + colBase + bSeg * 8);         \
        }                                                                          \
    };                                                                             \
    float acc[4][4][4];                                                            \
    _Pragma("unroll")                                                              \
    for (int i = 0; i < 4; i++)                                                    \
        _Pragma("unroll")                                                          \
        for (int j = 0; j < 4; j++)                                                \
            _Pragma("unroll")                                                      \
            for (int r = 0; r < 4; r++) acc[i][j][r] = 0.0f;                       \
    const int NITER = Kd >> 5;                                                     \
    load_stage(0, 0);  CP_COMMIT();                                                \
    load_stage(1, 32); CP_COMMIT();                                                \
    load_stage(2, 64); CP_COMMIT();                                                \
    for (int j = 0; j < NITER; j++) {                                              \
        CP_WAIT_GROUP(2);                                                          \
        __syncthreads();                                                           \
        if (j + 3 < NITER) load_stage((j + 3) & 3, (j + 3) * 32);                  \
        CP_COMMIT();                                                               \
        const uint32_t sA = sbase + (j & 3) * STAGE_NN;                            \
        const uint32_t sB = sA + OPH_BYTES;                                        \
        _Pragma("unroll")                                                          \
        for (int s = 0; s < 2; s++) {                                              \
            uint32_t af[4][4];                                                     \
            _Pragma("unroll")                                                      \
            for (int i = 0; i < 4; i++) {                                          \
                const uint32_t addr = sA + (((warpM * 64 + i * 16) * PADH) + s * 16 + aOff) * 2; \
                LDSM_X4(af[i][0], af[i][1], af[i][2], af[i][3], addr);             \
            }                                                                      \
            uint32_t bf[4][2];                                                     \
            _Pragma("unroll")                                                      \
            for (int p = 0; p < 2; p++) {                                          \
                const uint32_t addr = sB +                                         \
                    ((s * 16) * PADB + warpN * 32 + p * 16 + bOffT) * 2;           \
                LDSM_X4_T(bf[2 * p][0], bf[2 * p][1], bf[2 * p + 1][0], bf[2 * p + 1][1], addr); \
            }                                                                      \
            _Pragma("unroll")                                                      \
            for (int i = 0; i < 4; i++)                                            \
                _Pragma("unroll")                                                  \
                for (int jn = 0; jn < 4; jn++)                                     \
                    mma_f16(acc[i][jn], af[i][0], af[i][1], af[i][2], af[i][3],    \
                            bf[jn][0], bf[jn][1]);                                 \
        }                                                                          \
    }

// ---------------------------------------------------------------------------
// QKV projection, NN form, half out
// ---------------------------------------------------------------------------
__global__ void __launch_bounds__(256, 2)
h16_qkv_nn(const __half* __restrict__ A, const __half* __restrict__ B,
           __half* __restrict__ Cv, int Ntot, int Kd, int lda, int ldb)
{
    GEMM_NN_PROLOG()

#pragma unroll
    for (int i = 0; i < 4; i++) {
        const int r0 = rowBase + warpM * 64 + i * 16 + gID;
#pragma unroll
        for (int jn = 0; jn < 4; jn++) {
            const int c = colBase + warpN * 32 + jn * 8 + tig * 2;
#pragma unroll
            for (int half = 0; half < 2; half++) {
                const int r = r0 + half * 8;
                __half2 h = __floats2half2_rn(acc[i][jn][half * 2 + 0],
                                              acc[i][jn][half * 2 + 1]);
                *(__half2*)(Cv + (size_t)r * Ntot + c) = h;
            }
        }
    }
}

// ---------------------------------------------------------------------------
// PV GEMM, NN form: out = invS[r]*(P^ @ B + tRow[r]*cv[c])
// ---------------------------------------------------------------------------
__global__ void __launch_bounds__(256, 2)
h16_pv_nn(const __half* __restrict__ A, const __half* __restrict__ B,
          float* __restrict__ Cv, int Ntot, int Kd, int lda, int ldb,
          const float* __restrict__ invS, const float* __restrict__ tRow,
          const float* __restrict__ cvec)
{
    GEMM_NN_PROLOG()

#pragma unroll
    for (int i = 0; i < 4; i++) {
        const int r0 = rowBase + warpM * 64 + i * 16 + gID;
#pragma unroll
        for (int jn = 0; jn < 4; jn++) {
            const int c = colBase + warpN * 32 + jn * 8 + tig * 2;
#pragma unroll
            for (int half = 0; half < 2; half++) {
                const int r = r0 + half * 8;
                const float sc = invS[r];
                const float tr = tRow[r];
                float2 v;
                v.x = sc * (acc[i][jn][half * 2 + 0] + tr * cvec[c]);
                v.y = sc * (acc[i][jn][half * 2 + 1] + tr * cvec[c + 1]);
                *(float2*)(Cv + (size_t)r * Ntot + c) = v;
            }
        }
    }
}

// ---------------------------------------------------------------------------
// scores GEMM, NT, 128x64 tile (2048 CTAs -> 98.8% wave utilization)
// S = scale*(q~ k~^T + s_i*colAdd_j + z_i*s_j), fused rowMax
// ---------------------------------------------------------------------------
__global__ void __launch_bounds__(256, 2)
h16_scores64(const __half* __restrict__ A, const __half* __restrict__ B,
             float* __restrict__ Cv, int Ntot, int Kd, int lda, int ldb,
             float scale, const float* __restrict__ sRow,
             const float* __restrict__ colAdd, const float* __restrict__ zRow,
             unsigned* __restrict__ rowMax)
{
    extern __shared__ __half smh[];
    const uint32_t sbase = smem_u32(smh);

    const int gx = gridDim.x, gy = gridDim.y;
    const int lin = blockIdx.y * gx + blockIdx.x;
    const int GROUP = 8;
    const int per = GROUP * gx;
    const int g = lin / per;
    const int rem = lin - g * per;
    const int rowsLeft = gy - g * GROUP;
    const int rows = (GROUP < rowsLeft) ? GROUP : rowsLeft;
    const int byi = g * GROUP + rem % rows;
    const int bxi = rem / rows;

    const int tid  = threadIdx.x;
    const int lane = tid & 31;
    const int wid  = tid >> 5;
    const int warpM = wid >> 2;
    const int warpN = wid & 3;
    const int gID  = lane >> 2;
    const int tig  = lane & 3;
    const int rowBase = byi * 128;
    const int colBase = bxi * 64;

    const int lt = lane >> 3;
    const int l7 = lane & 7;
    const int aOff = ((lt & 1) * 8 + l7) * PADH + (lt >> 1) * 8;
    const int bOff = ((lt >> 1) * 8 + l7) * PADH + (lt & 1) * 8;

    const int ldRow0 = tid >> 2;          // A: 0..63 (+64)
    const int ldSeg  = tid & 3;
    const int bRow   = tid >> 2;          // B: 0..63 (one cp.async/thread)

    auto load_stage = [&](int st, int k0) {
        const uint32_t sA = sbase + st * STAGE_S64;
        const uint32_t sB = sA + OPH_BYTES;
#pragma unroll
        for (int i = 0; i < 2; i++) {
            const int row = ldRow0 + i * 64;
            CP_ASYNC16(sA + (row * PADH + ldSeg * 8) * 2,
                       A + (size_t)(rowBase + row) * lda + k0 + ldSeg * 8);
        }
        CP_ASYNC16(sB + (bRow * PADH + ldSeg * 8) * 2,
                   B + (size_t)(colBase + bRow) * ldb + k0 + ldSeg * 8);
    };

    float acc[4][2][4];
#pragma unroll
    for (int i = 0; i < 4; i++)
#pragma unroll
        for (int j = 0; j < 2; j++)
#pragma unroll
            for (int r = 0; r < 4; r++) acc[i][j][r] = 0.0f;

    const int NITER = Kd >> 5;

    load_stage(0, 0);  CP_COMMIT();
    load_stage(1, 32); CP_COMMIT();
    load_stage(2, 64); CP_COMMIT();

    for (int j = 0; j < NITER; j++) {
        CP_WAIT_GROUP(2);
        __syncthreads();
        if (j + 3 < NITER) load_stage((j + 3) & 3, (j + 3) * 32);
        CP_COMMIT();

        const uint32_t sA = sbase + (j & 3) * STAGE_S64;
        const uint32_t sB = sA + OPH_BYTES;

#pragma unroll
        for (int s = 0; s < 2; s++) {
            uint32_t af[4][4];
#pragma unroll
            for (int i = 0; i < 4; i++) {
                const uint32_t addr = sA + (((warpM * 64 + i * 16) * PADH) + s * 16 + aOff) * 2;
                LDSM_X4(af[i][0], af[i][1], af[i][2], af[i][3], addr);
            }
            uint32_t bf[2][2];
            {
                const uint32_t addr = sB + (((warpN * 16) * PADH) + s * 16 + bOff) * 2;
                LDSM_X4(bf[0][0], bf[0][1], bf[1][0], bf[1][1], addr);
            }
#pragma unroll
            for (int i = 0; i < 4; i++)
#pragma unroll
                for (int jn = 0; jn < 2; jn++)
                    mma_f16(acc[i][jn], af[i][0], af[i][1], af[i][2], af[i][3],
                            bf[jn][0], bf[jn][1]);
        }
    }

#pragma unroll
    for (int i = 0; i < 4; i++) {
        const int r0 = rowBase + warpM * 64 + i * 16 + gID;
#pragma unroll
        for (int half = 0; half < 2; half++) {
            const int r = r0 + half * 8;
            const float sr = sRow[r];
            const float zr = zRow[r];
            float vmax = -INFINITY;
#pragma unroll
            for (int jn = 0; jn < 2; jn++) {
                const int c = colBase + warpN * 16 + jn * 8 + tig * 2;
                float2 v;
                v.x = scale * (acc[i][jn][half * 2 + 0] + sr * colAdd[c]     + zr * sRow[c]);
                v.y = scale * (acc[i][jn][half * 2 + 1] + sr * colAdd[c + 1] + zr * sRow[c + 1]);
                *(float2*)(Cv + (size_t)r * Ntot + c) = v;
                vmax = fmaxf(vmax, fmaxf(v.x, v.y));
            }
            vmax = fmaxf(vmax, __shfl_xor_sync(0xFFFFFFFFu, vmax, 1));
            vmax = fmaxf(vmax, __shfl_xor_sync(0xFFFFFFFFu, vmax, 2));
            if (tig == 0) atomicMax(rowMax + r, fkey(vmax));
        }
    }
}

// ---------------------------------------------------------------------------
// column means of Wq, Wk, Wv -> a, b, cv
// ---------------------------------------------------------------------------
__global__ void __launch_bounds__(256)
colmean3(const float* __restrict__ Wq, const float* __restrict__ Wk,
         const float* __restrict__ Wv,
         float* __restrict__ a, float* __restrict__ b, float* __restrict__ cv)
{
    const float* W = (blockIdx.y == 0) ? Wq : (blockIdx.y == 1) ? Wk : Wv;
    float* o       = (blockIdx.y == 0) ? a  : (blockIdx.y == 1) ? b  : cv;
    __shared__ float red[8][33];
    const int tx = threadIdx.x & 31, ty = threadIdx.x >> 5;
    const int col = blockIdx.x * 32 + tx;
    float acc = 0.0f;
    for (int r = ty; r < DIN; r += 8)
        acc += W[(size_t)r * DOUT + col];
    red[ty][tx] = acc;
    __syncthreads();
    if (ty == 0) {
        float s = 0.0f;
#pragma unroll
        for (int k = 0; k < 8; k++) s += red[k][tx];
        o[col] = s * (1.0f / DIN);
    }
}

// a . b
__global__ void __launch_bounds__(256)
dotab(const float* __restrict__ a, const float* __restrict__ b, float* __restrict__ ab)
{
    __shared__ float red[256];
    float p = 0.0f;
    for (int i = threadIdx.x; i < DOUT; i += 256) p += a[i] * b[i];
    red[threadIdx.x] = p; __syncthreads();
    for (int s = 128; s > 0; s >>= 1) { if (threadIdx.x < s) red[threadIdx.x] += red[threadIdx.x + s]; __syncthreads(); }
    if (threadIdx.x == 0) ab[0] = red[0];
}

// gvec, 4 c-rows per block, 64 lanes/row, MLP-8
__global__ void __launch_bounds__(256)
gvec_raw4(const float* __restrict__ Wq, const float* __restrict__ Wk,
          const float* __restrict__ a, const float* __restrict__ b,
          float* __restrict__ gqr, float* __restrict__ gkr)
{
    __shared__ float s1[4][64], s2[4][64];
    const int t = threadIdx.x;
    const int rr = t >> 6;            // 0..3 row within block
    const int ln = t & 63;
    const int c = blockIdx.x * 4 + rr;
    const float4* wq4 = (const float4*)(Wq + (size_t)c * DOUT);
    const float4* wk4 = (const float4*)(Wk + (size_t)c * DOUT);
    const float4* a4  = (const float4*)a;
    const float4* b4  = (const float4*)b;
    float pq = 0.0f, pk = 0.0f;
#pragma unroll
    for (int i = 0; i < 4; i++) {
        const int idx = ln + i * 64;
        float4 wq = wq4[idx], wk = wk4[idx], bv = b4[idx], av = a4[idx];
        pq += wq.x * bv.x + wq.y * bv.y + wq.z * bv.z + wq.w * bv.w;
        pk += wk.x * av.x + wk.y * av.y + wk.z * av.z + wk.w * av.w;
    }
    s1[rr][ln] = pq; s2[rr][ln] = pk;
    __syncthreads();
    for (int st = 32; st > 0; st >>= 1) {
        if (ln < st) {
            s1[rr][ln] += s1[rr][ln + st];
            s2[rr][ln] += s2[rr][ln + st];
        }
        __syncthreads();
    }
    if (t < 4)             gqr[blockIdx.x * 4 + t] = s1[t][0];
    else if (t < 8)        gkr[blockIdx.x * 4 + (t - 4)] = s2[t - 4][0];
}

// szvec, 4 input rows per block, 64 lanes/row, MLP-12
__global__ void __launch_bounds__(256)
szvec4(const float* __restrict__ in, const float* __restrict__ gqr,
       const float* __restrict__ gkr, const float* __restrict__ ab,
       float* __restrict__ sRow, float* __restrict__ colAdd, float* __restrict__ zRow)
{
    __shared__ float s1[4][64], s2[4][64], s3[4][64];
    const int t = threadIdx.x;
    const int rr = t >> 6;
    const int ln = t & 63;
    const int i = blockIdx.x * 4 + rr;
    const float4* v4 = (const float4*)(in + (size_t)i * DIN);
    const float4* q4 = (const float4*)gqr;
    const float4* k4 = (const float4*)gkr;
    float s = 0.0f, z = 0.0f, w = 0.0f;
#pragma unroll
    for (int u = 0; u < 4; u++) {
        const int idx = ln + u * 64;
        float4 v = v4[idx], q = q4[idx], k = k4[idx];
        s += v.x + v.y + v.z + v.w;
        z += v.x * q.x + v.y * q.y + v.z * q.z + v.w * q.w;
        w += v.x * k.x + v.y * k.y + v.z * k.z + v.w * k.w;
    }
    s1[rr][ln] = s; s2[rr][ln] = z; s3[rr][ln] = w;
    __syncthreads();
    for (int st = 32; st > 0; st >>= 1) {
        if (ln < st) {
            s1[rr][ln] += s1[rr][ln + st];
            s2[rr][ln] += s2[rr][ln + st];
            s3[rr][ln] += s3[rr][ln + st];
        }
        __syncthreads();
    }
    if (ln == 0) {
        const int row = blockIdx.x * 4 + rr;
        sRow[row]   = s1[rr][0];
        zRow[row]   = s2[rr][0] - ab[0] * s1[rr][0];
        colAdd[row] = s3[rr][0];
    }
}

// f32 -> half convert, MLP-4; inits rowMax
__global__ void __launch_bounds__(256)
conv_h(const float* __restrict__ in, __half* __restrict__ out,
       unsigned* __restrict__ rowMax)
{
    const int t = blockIdx.x * 256 + threadIdx.x;
    const int chunk = gridDim.x * 256;
    if (t < SEQ) rowMax[t] = KEY_NEG_INF;
    const float4* in4 = (const float4*)in;
    float4 v0 = in4[t];
    float4 v1 = in4[t + chunk];
    float4 v2 = in4[t + 2 * chunk];
    float4 v3 = in4[t + 3 * chunk];
    __half2* o2 = (__half2*)out;
#pragma unroll
    for (int u = 0; u < 4; u++) {
        float4 v = (u == 0) ? v0 : (u == 1) ? v1 : (u == 2) ? v2 : v3;
        const int idx = t + u * chunk;
        o2[idx * 2]     = __floats2half2_rn(v.x, v.y);
        o2[idx * 2 + 1] = __floats2half2_rn(v.z, v.w);
    }
}

// center + convert W into NN layout, MLP-4
__global__ void __launch_bounds__(256)
center_w(const float* __restrict__ Wq, const float* __restrict__ Wk,
         const float* __restrict__ Wv, const float* __restrict__ a,
         const float* __restrict__ b, const float* __restrict__ cv,
         __half* __restrict__ Wall)
{
    const int z = blockIdx.y;
    const float* W   = (z == 0) ? Wq : (z == 1) ? Wk : Wv;
    const float* ctr = (z == 0) ? a : (z == 1) ? b : cv;

    const int t = blockIdx.x * 256 + threadIdx.x;
    const int chunk = gridDim.x * 256;          // 65536
    const float4* W4 = (const float4*)W;
    float4 w0 = W4[t], w1 = W4[t + chunk], w2 = W4[t + 2 * chunk], w3 = W4[t + 3 * chunk];
#pragma unroll
    for (int u = 0; u < 4; u++) {
        float4 w = (u == 0) ? w0 : (u == 1) ? w1 : (u == 2) ? w2 : w3;
        const int idx = t + u * chunk;
        const int k  = idx >> 8;
        const int d4 = idx & 255;
        float4 c = ((const float4*)ctr)[d4];
        __half2 h0 = __floats2half2_rn(w.x - c.x, w.y - c.y);
        __half2 h1 = __floats2half2_rn(w.z - c.z, w.w - c.w);
        __half* row = Wall + (size_t)k * (3 * DOUT) + z * DOUT + d4 * 4;
        *(__half2*)(row)     = h0;
        *(__half2*)(row + 2) = h1;
    }
}

// single-pass softmax, MLP-4: half unnorm P, invSum, tRow = sum exp*s
__global__ void __launch_bounds__(256)
softmax1t_kernel(const float* __restrict__ S, const unsigned* __restrict__ rowMaxKey,
                 const float* __restrict__ sRow,
                 __half* __restrict__ P, float* __restrict__ invSum,
                 float* __restrict__ tRow)
{
    __shared__ float sS[SEQ];
    __shared__ float red[256], redT[256];
    const int tid = threadIdx.x;
    {
        const float4* s4 = (const float4*)sRow;
        float4 a0 = s4[tid], a1 = s4[tid + 256], a2 = s4[tid + 512], a3 = s4[tid + 768];
        *(float4*)(sS + tid * 4)         = a0;
        *(float4*)(sS + (tid + 256) * 4) = a1;
        *(float4*)(sS + (tid + 512) * 4) = a2;
        *(float4*)(sS + (tid + 768) * 4) = a3;
    }
    __syncthreads();

    const float4* p4 = (const float4*)(S + (size_t)blockIdx.x * SEQ);
    __half* q = P + (size_t)blockIdx.x * SEQ;
    const float m = funkey(rowMaxKey[blockIdx.x]);

    float4 v0 = p4[tid], v1 = p4[tid + 256], v2 = p4[tid + 512], v3 = p4[tid + 768];

    float sum = 0.0f, tsum = 0.0f;
#pragma unroll
    for (int u = 0; u < 4; u++) {
        float4 v = (u == 0) ? v0 : (u == 1) ? v1 : (u == 2) ? v2 : v3;
        const int c = (tid + u * 256) * 4;
        __half2 e0 = __floats2half2_rn(expf(v.x - m), expf(v.y - m));
        __half2 e1 = __floats2half2_rn(expf(v.z - m), expf(v.w - m));
        *(__half2*)(q + c)     = e0;
        *(__half2*)(q + c + 2) = e1;
        float2 f0 = __half22float2(e0), f1 = __half22float2(e1);
        sum  += f0.x + f0.y + f1.x + f1.y;
        tsum += f0.x * sS[c] + f0.y * sS[c + 1] + f1.x * sS[c + 2] + f1.y * sS[c + 3];
    }
    red[tid] = sum; redT[tid] = tsum; __syncthreads();
    for (int s = 128; s > 0; s >>= 1) {
        if (tid < s) { red[tid] += red[tid + s]; redT[tid] += redT[tid + s]; }
        __syncthreads();
    }
    if (tid == 0) {
        invSum[blockIdx.x] = 1.0f / red[0];
        tRow[blockIdx.x]   = redT[0];
    }
}

// ---------------------------------------------------------------------------
extern "C" void kernel_launch(void* const* d_in, const int* in_sizes, int n_in,
                              void* d_out, int out_size)
{
    const float* input = (const float*)d_in[0];
    const float* Wq    = (const float*)d_in[1];
    const float* Wk    = (const float*)d_in[2];
    const float* Wv    = (const float*)d_in[3];
    float*       out   = (float*)d_out;

    __half *inH, *WallH, *QKVH, *PH;
    float *S, *invS, *tRow, *a, *b, *cv, *ab, *gqr, *gkr, *sRow, *colAdd, *zRow;
    unsigned* rowMax;
    cudaGetSymbolAddress((void**)&inH,    g_inH);
    cudaGetSymbolAddress((void**)&WallH,  g_WallH);
    cudaGetSymbolAddress((void**)&QKVH,   g_QKVH);
    cudaGetSymbolAddress((void**)&S,      g_S);
    cudaGetSymbolAddress((void**)&PH,     g_PH);
    cudaGetSymbolAddress((void**)&invS,   g_invS);
    cudaGetSymbolAddress((void**)&tRow,   g_tRow);
    cudaGetSymbolAddress((void**)&a,      g_a);
    cudaGetSymbolAddress((void**)&b,      g_b);
    cudaGetSymbolAddress((void**)&cv,     g_cv);
    cudaGetSymbolAddress((void**)&ab,     g_ab);
    cudaGetSymbolAddress((void**)&gqr,    g_gqr);
    cudaGetSymbolAddress((void**)&gkr,    g_gkr);
    cudaGetSymbolAddress((void**)&sRow,   g_sRow);
    cudaGetSymbolAddress((void**)&colAdd, g_colAdd);
    cudaGetSymbolAddress((void**)&zRow,   g_zRow);
    cudaGetSymbolAddress((void**)&rowMax, g_rowMax);

    const int smemNN  = NSTAGE_H * STAGE_NN;    // 75776
    const int smemS64 = NSTAGE_H * STAGE_S64;   // 61440
    cudaFuncSetAttribute(h16_qkv_nn,   cudaFuncAttributeMaxDynamicSharedMemorySize, smemNN);
    cudaFuncSetAttribute(h16_scores64, cudaFuncAttributeMaxDynamicSharedMemorySize, smemS64);
    cudaFuncSetAttribute(h16_pv_nn,    cudaFuncAttributeMaxDynamicSharedMemorySize, smemNN);

    const float scale = 1.0f / 32.0f;   // 1/sqrt(1024)
    dim3 gQKV(3 * DOUT / 128, SEQ / 128);
    dim3 gProj(DOUT / 128, SEQ / 128);
    dim3 gS(SEQ / 64, SEQ / 128);       // 64 x 32 = 2048 CTAs

    // 1-5: rank-one machinery + staging
    colmean3<<<dim3(DOUT / 32, 3), 256>>>(Wq, Wk, Wv, a, b, cv);
    conv_h<<<SEQ * DIN / 16 / 256, 256>>>(input, inH, rowMax);
    dotab<<<1, 256>>>(a, b, ab);
    gvec_raw4<<<DIN / 4, 256>>>(Wq, Wk, a, b, gqr, gkr);
    center_w<<<dim3(DIN * DOUT / 16 / 256, 3), 256>>>(Wq, Wk, Wv, a, b, cv, WallH);

    // 6: combined QKV projection (profiled)
    h16_qkv_nn<<<gQKV, 256, smemNN>>>(inH, WallH, QKVH, 3 * DOUT, DIN,
                                      DIN, 3 * DOUT);

    // 7: correction vectors
    szvec4<<<SEQ / 4, 256>>>(input, gqr, gkr, ab, sRow, colAdd, zRow);

    // 8: scores (128x64 tiles, 2048 CTAs), fused rowMax
    h16_scores64<<<gS, 256, smemS64>>>(QKVH, QKVH + DOUT, S, SEQ, DIN,
                                       3 * DOUT, 3 * DOUT,
                                       scale, sRow, colAdd, zRow, rowMax);

    // 9: softmax (single pass): P^, invSum, tRow
    softmax1t_kernel<<<SEQ, 256>>>(S, rowMax, sRow, PH, invS, tRow);

    // 10: out = invS * (P^ @ v~ + tRow * cv^T), NN form
    h16_pv_nn<<<gProj, 256, smemNN>>>(PH, QKVH + 2 * DOUT, out, DOUT, SEQ,
                                      SEQ, 3 * DOUT, invS, tRow, cv);
}